// round 17
// baseline (speedup 1.0000x reference)
#include <cuda_runtime.h>
#include <math.h>

#define B 32
#define T 512
#define U 1024
#define E 1024
#define DIN 256
#define G4 4096        // 4*U
#define NSPL_IND 10    // independent z chunks (2 inputs + 8 h), k=128 each
#define NSPL_CTX 16    // context z chunks, k=64 each
#define NSPL (NSPL_IND + NSPL_CTX)
#define NTILE 1024     // P24 tiles: b(32) x sl(32 slices of 16 t)
#define NCTXP 64       // context partials (two tsub halves per slice)
#define GRID 296       // 148 SMs x 2 resident blocks
#define NT 512

// ---------------- scratch (device globals: no allocations allowed) ----------
__device__ float g_qpart[16 * B * U];
__device__ float g_query[B * U];
__device__ float g_tsum[B * 32];           // per-slice exp sums (deterministic)
__device__ float g_ctxpart[NCTXP * B * E]; // unnormalized context partials
__device__ float g_context[B * E];
__device__ float g_zpart[NSPL * B * G4];
__device__ unsigned int g_count = 0;  // barrier counter (self-resets)
__device__ unsigned int g_gen = 0;    // barrier generation (monotonic)

// ---------------- helpers ----------------------------------------------------
__device__ __forceinline__ unsigned long long pack2(float a, float b) {
    unsigned long long r;
    asm("mov.b64 %0, {%1, %2};" : "=l"(r) : "r"(__float_as_uint(a)), "r"(__float_as_uint(b)));
    return r;
}
__device__ __forceinline__ void unpack2(unsigned long long v, float& a, float& b) {
    unsigned int lo, hi;
    asm("mov.b64 {%0, %1}, %2;" : "=r"(lo), "=r"(hi) : "l"(v));
    a = __uint_as_float(lo); b = __uint_as_float(hi);
}
__device__ __forceinline__ unsigned long long fma2(unsigned long long x,
                                                   unsigned long long y,
                                                   unsigned long long a) {
    unsigned long long d;
    asm("fma.rn.f32x2 %0, %1, %2, %3;" : "=l"(d) : "l"(x), "l"(y), "l"(a));
    return d;
}
__device__ __forceinline__ float tanh_hw(float x) {
    float y;
    asm("tanh.approx.f32 %0, %1;" : "=f"(y) : "f"(x));
    return y;
}
__device__ __forceinline__ float sigmoid_acc(float x) {
    return 1.0f / (1.0f + expf(-x));
}
__device__ __forceinline__ float4 ldcs4(const float4* p) {
    float4 v;
    asm("ld.global.cs.v4.f32 {%0,%1,%2,%3}, [%4];"
        : "=f"(v.x), "=f"(v.y), "=f"(v.z), "=f"(v.w) : "l"(p));
    return v;
}

// Grid-wide barrier: counter + monotonic generation (replay-safe).
__device__ __forceinline__ void grid_barrier() {
    __syncthreads();
    if (threadIdx.x == 0) {
        __threadfence();
        unsigned int gen = atomicAdd(&g_gen, 0u);
        unsigned int arrived = atomicAdd(&g_count, 1u) + 1u;
        if (arrived == GRID) {
            g_count = 0;
            __threadfence();
            atomicAdd(&g_gen, 1u);
        } else {
            while (atomicAdd(&g_gen, 0u) == gen) { __nanosleep(64); }
        }
        __threadfence();
    }
    __syncthreads();
}

// ---------------- the whole cell: pipelined attention stream ------------------
__global__ void __launch_bounds__(NT, 2) mono_cell(
    const float* __restrict__ inputs, const float* __restrict__ h,
    const float* __restrict__ c, const float* __restrict__ se,
    const float* __restrict__ es, const float* __restrict__ Wa,
    const float* __restrict__ Wa_b, const float* __restrict__ va_w,
    const float* __restrict__ va_b, const float* __restrict__ Wk,
    const float* __restrict__ Wr, const float* __restrict__ bias,
    float* __restrict__ out)
{
    __shared__ __align__(16) float pool[128 * 36];   // 18.4KB, reused per phase
    const int tid = threadIdx.x;
    const int bx = blockIdx.x;
    const int gtid = bx * NT + tid;

    // ===== P1: query partials (64 blk) + independent z partials (160 blk) =====
    if (bx < 64) {
        const int tile = bx >> 4, kb = bx & 15;
        const int k0 = kb * 64;
        const int u = tile * 256 + (tid & 255);
        const int bh = tid >> 8;

        for (int idx = tid; idx < 32 * 64; idx += NT) {
            int b = idx >> 6, k = idx & 63;
            pool[k * 36 + b] = h[b * U + k0 + k];
        }
        __syncthreads();

        unsigned long long acc[8];
#pragma unroll
        for (int p = 0; p < 8; p++) acc[p] = 0ull;
        const float* wcol = Wa + (size_t)k0 * U + u;
#pragma unroll 8
        for (int k = 0; k < 64; k++) {
            float w = wcol[(size_t)k * U];
            unsigned long long ww = pack2(w, w);
            const unsigned long long* xp =
                reinterpret_cast<const unsigned long long*>(&pool[k * 36]) + bh * 8;
#pragma unroll
            for (int p = 0; p < 8; p++) acc[p] = fma2(xp[p], ww, acc[p]);
        }
        float* outp = g_qpart + (size_t)kb * (B * U);
#pragma unroll
        for (int p = 0; p < 8; p++) {
            float a, b2; unpack2(acc[p], a, b2);
            outp[(bh * 16 + 2 * p) * U + u] = a;
            outp[(bh * 16 + 2 * p + 1) * U + u] = b2;
        }
    } else if (bx < 64 + 160) {
        const int zi = bx - 64;
        const int kb = zi >> 4, jt = zi & 15;
        const int j = jt * 256 + (tid & 255);
        const int bh = tid >> 8;

        const float* xsrc; int x_ld, xk0;
        const float* W;    int wk0;
        if (kb < 2) { xsrc = inputs; x_ld = DIN; xk0 = kb * 128;       W = Wk; wk0 = kb * 128; }
        else        { xsrc = h;      x_ld = U;   xk0 = (kb - 2) * 128; W = Wr; wk0 = (kb - 2) * 128; }

        for (int idx = tid; idx < 32 * 128; idx += NT) {
            int b = idx >> 7, kk = idx & 127;
            pool[kk * 36 + b] = xsrc[(size_t)b * x_ld + xk0 + kk];
        }
        __syncthreads();

        unsigned long long acc[8];
#pragma unroll
        for (int p = 0; p < 8; p++) acc[p] = 0ull;
        const float* wcol = W + (size_t)wk0 * G4 + j;
#pragma unroll 8
        for (int kk = 0; kk < 128; kk++) {
            float w = wcol[(size_t)kk * G4];
            unsigned long long ww = pack2(w, w);
            const unsigned long long* xp =
                reinterpret_cast<const unsigned long long*>(&pool[kk * 36]) + bh * 8;
#pragma unroll
            for (int p = 0; p < 8; p++) acc[p] = fma2(xp[p], ww, acc[p]);
        }
        float* outp = g_zpart + (size_t)kb * (B * G4);
#pragma unroll
        for (int p = 0; p < 8; p++) {
            float a, b2; unpack2(acc[p], a, b2);
            outp[(size_t)(bh * 16 + 2 * p) * G4 + j] = a;
            outp[(size_t)(bh * 16 + 2 * p + 1) * G4 + j] = b2;
        }
    }
    grid_barrier();

    // ===== P1b: reduce query partials + bias ==================================
    if (gtid < B * U) {
        float s = Wa_b[gtid & (U - 1)];
#pragma unroll
        for (int kb = 0; kb < 16; kb++) s += g_qpart[kb * (B * U) + gtid];
        g_query[gtid] = s;
    }
    grid_barrier();

    // ===== P24 pipelined: logits(k+1) overlap context-FMA(k); 1 sync/tile =====
    {
        float4* vs4 = reinterpret_cast<float4*>(pool);   // va: 256 float4
        float* psA = pool + 1024;                        // 16 exp(logit)
        float* psB = pool + 1040;
        const float vb = va_b[0];
        const int w = tid >> 5, lane = tid & 31;
        const int tsub = tid >> 8, e4 = tid & 255;

        for (int i4 = tid; i4 < 256; i4 += NT)
            vs4[i4] = reinterpret_cast<const float4*>(va_w)[i4];
        __syncthreads();   // vs4 visible before any logits

        // logits for one 16-row slice; q via __ldg (L2-hot), va from smem
        auto logits_into = [&](int tile, float* psbuf) {
            const int b = tile >> 5, sl = tile & 31;
            const float4* erow = reinterpret_cast<const float4*>(es)
                               + (size_t)(b * T + sl * 16 + w) * 256;
            const float4* qrow = reinterpret_cast<const float4*>(g_query + b * U);
            float s = 0.f;
#pragma unroll
            for (int ch = 0; ch < 2; ch++) {
                float4 e[4];
#pragma unroll
                for (int i = 0; i < 4; i++) e[i] = ldcs4(&erow[lane + (ch * 4 + i) * 32]);
#pragma unroll
                for (int i = 0; i < 4; i++) {
                    int u4 = lane + (ch * 4 + i) * 32;
                    float4 q4 = __ldg(&qrow[u4]);
                    float4 v4 = vs4[u4];
                    s += tanh_hw(q4.x + e[i].x) * v4.x;
                    s += tanh_hw(q4.y + e[i].y) * v4.y;
                    s += tanh_hw(q4.z + e[i].z) * v4.z;
                    s += tanh_hw(q4.w + e[i].w) * v4.w;
                }
            }
#pragma unroll
            for (int o = 16; o; o >>= 1) s += __shfl_xor_sync(0xffffffffu, s, o);
            if (lane == 0) psbuf[w] = __expf(s + vb);    // logits are O(1): safe
        };

        float* cur = psA;
        float* nxt = psB;
        if (bx < NTILE) logits_into(bx, cur);            // prologue

        for (int tile = bx; tile < NTILE; tile += GRID) {
            const int b = tile >> 5, sl = tile & 31;

            // se loads for THIS tile (overlap next tile's logits below)
            const float4* se4 = reinterpret_cast<const float4*>(se)
                              + ((size_t)(b * T + sl * 16 + tsub * 8)) * 256 + e4;
            float4 v[8];
#pragma unroll
            for (int i = 0; i < 8; i++) v[i] = ldcs4(&se4[(size_t)i * 256]);

            __syncthreads();   // cur ps (written pre-loop or last iter) visible

            const int ntile = tile + GRID;
            if (ntile < NTILE) logits_into(ntile, nxt);  // overlaps v latency

            if (tid == 0) {
                float ts = 0.f;
#pragma unroll
                for (int i = 0; i < 16; i++) ts += cur[i];
                g_tsum[b * 32 + sl] = ts;                // deterministic
            }

            const float* ap = cur + tsub * 8;
            float4 acc = make_float4(0.f, 0.f, 0.f, 0.f);
#pragma unroll
            for (int i = 0; i < 8; i++) {
                float pw = ap[i];
                acc.x += pw * v[i].x; acc.y += pw * v[i].y;
                acc.z += pw * v[i].z; acc.w += pw * v[i].w;
            }
            reinterpret_cast<float4*>(g_ctxpart)
                [(size_t)((sl * 2 + tsub) * B + b) * 256 + e4] = acc;

            float* tmp = cur; cur = nxt; nxt = tmp;      // swap ps buffers
        }
    }
    grid_barrier();

    // ===== P5: reduce 64 context partials + normalize by esum =================
    if (bx < 64) {
        const int b = bx >> 1;
        const int eoff = (bx & 1) * 512;
        if (tid < 32) pool[tid] = g_tsum[b * 32 + tid];
        __syncthreads();
        if (tid == 0) {
            float s = 0.f;
#pragma unroll
            for (int i = 0; i < 32; i++) s += pool[i];
            pool[32] = 1.0f / s;
        }
        __syncthreads();
        const float inv = pool[32];
        const int e = eoff + tid;
        float s = 0.f;
#pragma unroll
        for (int pp = 0; pp < NCTXP; pp++) s += g_ctxpart[(size_t)(pp * B + b) * E + e];
        g_context[b * E + e] = s * inv;
    }
    grid_barrier();

    // ===== P6: z-ctx partials; 256 blocks = kb(16 of k=64) x jt(16 of j=256) ==
    if (bx < 256) {
        const int kb = bx >> 4, jt = bx & 15;
        const int j = jt * 256 + (tid & 255);
        const int bh = tid >> 8;
        const int k0 = kb * 64;

        for (int idx = tid; idx < 32 * 64; idx += NT) {
            int b = idx >> 6, kk = idx & 63;
            pool[kk * 36 + b] = g_context[(size_t)b * E + k0 + kk];
        }
        __syncthreads();

        unsigned long long acc[8];
#pragma unroll
        for (int p = 0; p < 8; p++) acc[p] = 0ull;
        const float* wcol = Wk + (size_t)(DIN + k0) * G4 + j;
#pragma unroll 8
        for (int kk = 0; kk < 64; kk++) {
            float w = wcol[(size_t)kk * G4];
            unsigned long long ww = pack2(w, w);
            const unsigned long long* xp =
                reinterpret_cast<const unsigned long long*>(&pool[kk * 36]) + bh * 8;
#pragma unroll
            for (int p = 0; p < 8; p++) acc[p] = fma2(xp[p], ww, acc[p]);
        }
        float* outp = g_zpart + (size_t)(NSPL_IND + kb) * (B * G4);
#pragma unroll
        for (int p = 0; p < 8; p++) {
            float a, b2; unpack2(acc[p], a, b2);
            outp[(size_t)(bh * 16 + 2 * p) * G4 + j] = a;
            outp[(size_t)(bh * 16 + 2 * p + 1) * G4 + j] = b2;
        }
    }
    grid_barrier();

    // ===== P7: reduce z partials + bias, gates, outputs =======================
    if (gtid < B * U) {
        const int b = gtid >> 10, u = gtid & (U - 1);
        float z[4];
#pragma unroll
        for (int g = 0; g < 4; g++) {
            int col = g * U + u;
            float s = bias[col];
            const float* zp = g_zpart + (size_t)b * G4 + col;
#pragma unroll
            for (int kb = 0; kb < NSPL; kb++)
                s += zp[(size_t)kb * (B * G4)];
            z[g] = s;
        }
        float c_new = sigmoid_acc(z[1]) * c[gtid] + sigmoid_acc(z[0]) * tanhf(z[2]);
        float h_new = sigmoid_acc(z[3]) * tanhf(c_new);
        out[gtid]             = h_new;  // lstmout
        out[B * U + gtid]     = h_new;  // h state
        out[2 * B * U + gtid] = c_new;  // c state
    }
}

// ---------------- launcher ------------------------------------------------------
extern "C" void kernel_launch(void* const* d_in, const int* in_sizes, int n_in,
                              void* d_out, int out_size) {
    const float* inputs      = (const float*)d_in[0];
    const float* h           = (const float*)d_in[1];
    const float* c           = (const float*)d_in[2];
    const float* speech_enc  = (const float*)d_in[3];
    const float* encodestate = (const float*)d_in[4];
    const float* Wa_w        = (const float*)d_in[5];
    const float* Wa_b        = (const float*)d_in[6];
    const float* va_w        = (const float*)d_in[7];
    const float* va_b        = (const float*)d_in[8];
    const float* kernel_w    = (const float*)d_in[9];
    const float* rec_kernel  = (const float*)d_in[10];
    const float* bias        = (const float*)d_in[11];
    float* out = (float*)d_out;

    mono_cell<<<GRID, NT>>>(inputs, h, c, speech_enc, encodestate,
                            Wa_w, Wa_b, va_w, va_b,
                            kernel_w, rec_kernel, bias, out);
}